// round 1
// baseline (speedup 1.0000x reference)
#include <cuda_runtime.h>
#include <cstdint>

// Problem constants
#define B_ROWS 4096     // batch
#define IN_DIM 512
#define OUT_DIM 256
#define U_ROWS 8192     // 2 * B_ROWS

// ---------------- scratch (device globals; no runtime allocation) ----------------
__device__ float  g_U[(size_t)U_ROWS * OUT_DIM];  // outs, [l*4096+b][o]  (8 MB)
__device__ float  g_sq[U_ROWS];                    // per-row squared norms
__device__ float  g_colsum[OUT_DIM];               // column sums of U
__device__ float  g_sumsq;                         // sum of g_sq
__device__ double g_loss;                          // signed kernel-sum accumulator
__device__ float  g_coef;                          // -log2(e) / (4 * bandwidth_base)

// ---------------- kernel 0: zero accumulators (needed every graph replay) --------
__global__ void k_zero() {
    int t = threadIdx.x;
    if (t < OUT_DIM) g_colsum[t] = 0.f;
    if (t == 0) { g_sumsq = 0.f; g_loss = 0.0; }
}

// ---------------- kernel 1: outs GEMM  C = x @ Wcat^T + bias  -> g_U -------------
// x: [4096,512], W viewed as Wcat: [512,512] (row = l*256+o), bias: [512]
// 128x128 tile, BK=16, 256 threads, 8x8 microtile.
__global__ __launch_bounds__(256, 2) void k_outs(const float* __restrict__ x,
                                                 const float* __restrict__ W,
                                                 const float* __restrict__ bias) {
    __shared__ float As[16][128];  // [k][m]
    __shared__ float Bs[16][128];  // [k][n]
    const int tid = threadIdx.x;
    const int tx = tid & 15, ty = tid >> 4;
    const int bm = blockIdx.y, bn = blockIdx.x;

    float acc[8][8];
#pragma unroll
    for (int r = 0; r < 8; r++)
#pragma unroll
        for (int c = 0; c < 8; c++) acc[r][c] = 0.f;

    for (int k0 = 0; k0 < IN_DIM; k0 += 16) {
#pragma unroll
        for (int s = 0; s < 2; s++) {
            int idx = tid + s * 256;
            int row = idx >> 2;
            int c4  = (idx & 3) << 2;
            float4 av = *(const float4*)(x + (size_t)(bm * 128 + row) * IN_DIM + k0 + c4);
            As[c4 + 0][row] = av.x; As[c4 + 1][row] = av.y;
            As[c4 + 2][row] = av.z; As[c4 + 3][row] = av.w;
            float4 bv = *(const float4*)(W + (size_t)(bn * 128 + row) * IN_DIM + k0 + c4);
            Bs[c4 + 0][row] = bv.x; Bs[c4 + 1][row] = bv.y;
            Bs[c4 + 2][row] = bv.z; Bs[c4 + 3][row] = bv.w;
        }
        __syncthreads();
#pragma unroll
        for (int k = 0; k < 16; k++) {
            float4 alo = *(const float4*)&As[k][ty * 4];
            float4 ahi = *(const float4*)&As[k][ty * 4 + 64];
            float4 blo = *(const float4*)&Bs[k][tx * 4];
            float4 bhi = *(const float4*)&Bs[k][tx * 4 + 64];
            float a[8] = {alo.x, alo.y, alo.z, alo.w, ahi.x, ahi.y, ahi.z, ahi.w};
            float b[8] = {blo.x, blo.y, blo.z, blo.w, bhi.x, bhi.y, bhi.z, bhi.w};
#pragma unroll
            for (int r = 0; r < 8; r++)
#pragma unroll
                for (int c = 0; c < 8; c++) acc[r][c] = fmaf(a[r], b[c], acc[r][c]);
        }
        __syncthreads();
    }

#pragma unroll
    for (int r = 0; r < 8; r++) {
        int m = bm * 128 + ty * 4 + (r < 4 ? r : 60 + r);
#pragma unroll
        for (int c = 0; c < 8; c++) {
            int n = bn * 128 + tx * 4 + (c < 4 ? c : 60 + c);
            int l = n >> 8, o = n & 255;
            g_U[((size_t)(l * B_ROWS + m)) * OUT_DIM + o] = acc[r][c] + bias[n];
        }
    }
}

// ---------------- kernel 2: per-row sq norms, colsums, sumsq ---------------------
__global__ void k_rowstats() {
    const int tid = threadIdx.x;            // 256 threads
    const int r0  = blockIdx.x * 128;       // 64 blocks x 128 rows

    // column sums (coalesced: thread = column)
    float cs = 0.f;
    for (int r = 0; r < 128; r++) cs += g_U[(size_t)(r0 + r) * OUT_DIM + tid];
    atomicAdd(&g_colsum[tid], cs);

    // per-row squared norms (warp per row)
    int w = tid >> 5, lane = tid & 31;
    float warpsq = 0.f;
    for (int rr = w; rr < 128; rr += 8) {
        const float* row = g_U + (size_t)(r0 + rr) * OUT_DIM;
        float s = 0.f;
#pragma unroll
        for (int c = lane; c < OUT_DIM; c += 32) { float v = row[c]; s = fmaf(v, v, s); }
#pragma unroll
        for (int off = 16; off; off >>= 1) s += __shfl_down_sync(0xffffffffu, s, off);
        if (lane == 0) { g_sq[r0 + rr] = s; warpsq += s; }
    }
    if (lane == 0) atomicAdd(&g_sumsq, warpsq);
}

// ---------------- kernel 3: bandwidth -> exp coefficient -------------------------
__global__ void k_bw() {
    __shared__ float red[256];
    int t = threadIdx.x;
    float c = g_colsum[t];
    red[t] = c * c;
    __syncthreads();
    for (int s = 128; s; s >>= 1) { if (t < s) red[t] += red[t + s]; __syncthreads(); }
    if (t == 0) {
        double s2 = (double)red[0];
        double sumsq = (double)g_sumsq;
        double n = (double)U_ROWS;
        double bw = (2.0 * n * sumsq - 2.0 * s2) / (n * (n - 1.0));
        // exponent coef: exp(-d/(4*bw)) computed via exp2; chain-square for 5 bands
        g_coef = (float)(-1.4426950408889634 / (4.0 * bw));
    }
}

// ---------------- kernel 4: gates (softmax over 2) + combine -> d_out ------------
__global__ void k_gates(const float* __restrict__ x, const float* __restrict__ Waux,
                        const float* __restrict__ baux, float* __restrict__ out) {
    __shared__ float r0s[128], r1s[128];
    const int b = blockIdx.x, t = threadIdx.x;  // 128 threads
    float p0 = 0.f, p1 = 0.f;
#pragma unroll
    for (int s = 0; s < 4; s++) {
        float xv = x[(size_t)b * IN_DIM + t + s * 128];
        p0 = fmaf(xv, Waux[t + s * 128], p0);
        p1 = fmaf(xv, Waux[IN_DIM + t + s * 128], p1);
    }
    r0s[t] = p0; r1s[t] = p1;
    __syncthreads();
    for (int s = 64; s; s >>= 1) {
        if (t < s) { r0s[t] += r0s[t + s]; r1s[t] += r1s[t + s]; }
        __syncthreads();
    }
    float l0 = r0s[0] + baux[0];
    float l1 = r1s[0] + baux[1];
    float gg0 = 1.f / (1.f + expf(l1 - l0));
    float gg1 = 1.f - gg0;
#pragma unroll
    for (int s = 0; s < 2; s++) {
        int c = t + s * 128;
        float v = gg0 * g_U[(size_t)b * OUT_DIM + c] +
                  gg1 * g_U[(size_t)(B_ROWS + b) * OUT_DIM + c];
        out[(size_t)b * OUT_DIM + c] = v;
    }
}

// ---------------- kernel 5: pairwise Gram + multi-band kernel sum ----------------
// Upper-triangle 128x128 tiles over U (8192x256). Per pair:
//   d = sq[i]+sq[j]-2*dot;  u = exp2(coef*d);  F = u+u^2+u^4+u^8+u^16
//   contribution = sign * weight * F  (sign = +1 same side, -1 cross; w=2 off-diag)
__global__ __launch_bounds__(256, 2) void k_pair() {
    const int bi = blockIdx.y, bj = blockIdx.x;
    if (bj < bi) return;

    __shared__ float As[16][128];
    __shared__ float Bs[16][128];
    __shared__ float sqI[128], sqJ[128];
    __shared__ float red[256];

    const int tid = threadIdx.x;
    const int tx = tid & 15, ty = tid >> 4;

    if (tid < 128) {
        sqI[tid] = g_sq[bi * 128 + tid];
        sqJ[tid] = g_sq[bj * 128 + tid];
    }

    float acc[8][8];
#pragma unroll
    for (int r = 0; r < 8; r++)
#pragma unroll
        for (int c = 0; c < 8; c++) acc[r][c] = 0.f;

    for (int k0 = 0; k0 < OUT_DIM; k0 += 16) {
#pragma unroll
        for (int s = 0; s < 2; s++) {
            int idx = tid + s * 256;
            int row = idx >> 2;
            int c4  = (idx & 3) << 2;
            float4 av = *(const float4*)(g_U + (size_t)(bi * 128 + row) * OUT_DIM + k0 + c4);
            As[c4 + 0][row] = av.x; As[c4 + 1][row] = av.y;
            As[c4 + 2][row] = av.z; As[c4 + 3][row] = av.w;
            float4 bv = *(const float4*)(g_U + (size_t)(bj * 128 + row) * OUT_DIM + k0 + c4);
            Bs[c4 + 0][row] = bv.x; Bs[c4 + 1][row] = bv.y;
            Bs[c4 + 2][row] = bv.z; Bs[c4 + 3][row] = bv.w;
        }
        __syncthreads();
#pragma unroll
        for (int k = 0; k < 16; k++) {
            float4 alo = *(const float4*)&As[k][ty * 4];
            float4 ahi = *(const float4*)&As[k][ty * 4 + 64];
            float4 blo = *(const float4*)&Bs[k][tx * 4];
            float4 bhi = *(const float4*)&Bs[k][tx * 4 + 64];
            float a[8] = {alo.x, alo.y, alo.z, alo.w, ahi.x, ahi.y, ahi.z, ahi.w};
            float b[8] = {blo.x, blo.y, blo.z, blo.w, bhi.x, bhi.y, bhi.z, bhi.w};
#pragma unroll
            for (int r = 0; r < 8; r++)
#pragma unroll
                for (int c = 0; c < 8; c++) acc[r][c] = fmaf(a[r], b[c], acc[r][c]);
        }
        __syncthreads();
    }

    const float coef = g_coef;
    const float sgn  = ((bi < 32) == (bj < 32)) ? 1.f : -1.f;
    const bool  diag = (bi == bj);

    float local = 0.f;
#pragma unroll
    for (int r = 0; r < 8; r++) {
        int mi = ty * 4 + (r < 4 ? r : 60 + r);
#pragma unroll
        for (int c = 0; c < 8; c++) {
            int nj = tx * 4 + (c < 4 ? c : 60 + c);
            float w = 2.f;
            if (diag) w = (nj > mi) ? 2.f : (nj == mi ? 1.f : 0.f);
            float d = sqI[mi] + sqJ[nj] - 2.f * acc[r][c];
            float e = coef * d;
            float u;
            asm("ex2.approx.f32 %0, %1;" : "=f"(u) : "f"(e));
            float u2 = u * u, u4 = u2 * u2, u8 = u4 * u4, u16 = u8 * u8;
            local += w * (u + u2 + u4 + u8 + u16);
        }
    }
    red[tid] = local * sgn;
    __syncthreads();
    for (int s = 128; s; s >>= 1) { if (tid < s) red[tid] += red[tid + s]; __syncthreads(); }
    if (tid == 0) atomicAdd(&g_loss, (double)red[0]);
}

// ---------------- kernel 6: final scalar ----------------------------------------
__global__ void k_final(float* __restrict__ out, int idx) {
    if (threadIdx.x == 0)
        out[idx] = (float)(-g_loss / ((double)B_ROWS * (double)B_ROWS));
}

// ---------------- launch ----------------------------------------------------------
extern "C" void kernel_launch(void* const* d_in, const int* in_sizes, int n_in,
                              void* d_out, int out_size) {
    const float* x    = (const float*)d_in[0];  // [4096,512]
    const float* Waux = (const float*)d_in[1];  // [2,512]
    const float* baux = (const float*)d_in[2];  // [2]
    const float* W    = (const float*)d_in[3];  // [2,256,512] == [512,512]
    const float* bias = (const float*)d_in[4];  // [2,256] == [512]
    float* out = (float*)d_out;

    k_zero<<<1, 256>>>();
    k_outs<<<dim3(4, 32), 256>>>(x, W, bias);
    k_rowstats<<<64, 256>>>();
    k_bw<<<1, 256>>>();
    k_gates<<<B_ROWS, 128>>>(x, Waux, baux, out);
    k_pair<<<dim3(64, 64), 256>>>();
    k_final<<<1, 1>>>(out, out_size - 1);
}

// round 3
// speedup vs baseline: 2.0366x; 2.0366x over previous
#include <cuda_runtime.h>
#include <cuda_bf16.h>
#include <cstdint>

#define B_ROWS 4096
#define IN_DIM 512
#define OUT_DIM 256
#define U_ROWS 8192

// ---------------- scratch ----------------
__device__ float          g_U [(size_t)U_ROWS * OUT_DIM];
__device__ __nv_bfloat16  g_Uh[(size_t)U_ROWS * OUT_DIM];
__device__ __nv_bfloat16  g_Ul[(size_t)U_ROWS * OUT_DIM];
__device__ __nv_bfloat16  g_xh[(size_t)B_ROWS * IN_DIM];
__device__ __nv_bfloat16  g_xl[(size_t)B_ROWS * IN_DIM];
__device__ __nv_bfloat16  g_Wh[512 * IN_DIM];
__device__ __nv_bfloat16  g_Wl[512 * IN_DIM];
__device__ float  g_sq[U_ROWS];
__device__ float  g_colsum[OUT_DIM];
__device__ float  g_sumsq;
__device__ double g_loss;
__device__ float  g_coef;

// ---------------- helpers (sm_80-era, family-common PTX only) ----------------
__device__ __forceinline__ uint32_t smem_u32(const void* p) {
    uint32_t a;
    asm("{ .reg .u64 t; cvta.to.shared.u64 t, %1; cvt.u32.u64 %0, t; }" : "=r"(a) : "l"(p));
    return a;
}
__device__ __forceinline__ void ldsm4(uint32_t (&r)[4], uint32_t a) {
    asm volatile("ldmatrix.sync.aligned.m8n8.x4.shared.b16 {%0,%1,%2,%3}, [%4];"
                 : "=r"(r[0]), "=r"(r[1]), "=r"(r[2]), "=r"(r[3]) : "r"(a));
}
__device__ __forceinline__ void mma16816(float* c, const uint32_t* a, uint32_t b0, uint32_t b1) {
    asm volatile("mma.sync.aligned.m16n8k16.row.col.f32.bf16.bf16.f32 "
                 "{%0,%1,%2,%3},{%4,%5,%6,%7},{%8,%9},{%0,%1,%2,%3};"
                 : "+f"(c[0]), "+f"(c[1]), "+f"(c[2]), "+f"(c[3])
                 : "r"(a[0]), "r"(a[1]), "r"(a[2]), "r"(a[3]), "r"(b0), "r"(b1));
}
__device__ __forceinline__ void cp16(uint32_t d, const void* s) {
    asm volatile("cp.async.cg.shared.global [%0], [%1], 16;" :: "r"(d), "l"(s));
}
#define CP_COMMIT() asm volatile("cp.async.commit_group;" ::: "memory")
#define CP_WAIT(n)  asm volatile("cp.async.wait_group %0;" :: "n"(n) : "memory")

// smem layout: per buffer-set: Ah, Al, Bh, Bl; each [128 rows][72 bf16] (144 B rows)
#define ROWB   144
#define ARR    18432        // 128 * 144
#define SETSZ  73728        // 4 * ARR
#define DYNSZ  147456       // 2 buffer sets

template <int STRIDE>
__device__ __forceinline__ void load_chunk(uint32_t sbase,
    const __nv_bfloat16* Ah, const __nv_bfloat16* Al,
    const __nv_bfloat16* Bh, const __nv_bfloat16* Bl, int k0, int tid)
{
    const int row0 = tid >> 3;
    const int c    = (tid & 7) * 8;
#pragma unroll
    for (int pass = 0; pass < 4; pass++) {
        const int row = row0 + pass * 32;
        const size_t go = (size_t)row * STRIDE + k0 + c;
        const uint32_t so = (uint32_t)(row * ROWB + c * 2);
        cp16(sbase + 0 * ARR + so, Ah + go);
        cp16(sbase + 1 * ARR + so, Al + go);
        cp16(sbase + 2 * ARR + so, Bh + go);
        cp16(sbase + 3 * ARR + so, Bl + go);
    }
}

__device__ __forceinline__ void compute_chunk(uint32_t sbase, int wm, int wn, int lane,
                                              float (&acc)[2][8][4])
{
    const uint32_t lrow  = (uint32_t)(lane & 15);
    const uint32_t khalf = (uint32_t)((lane >> 4) * 16);
#pragma unroll
    for (int ks = 0; ks < 4; ks++) {
        const uint32_t kb = (uint32_t)(ks * 32) + khalf;
        uint32_t ah[2][4], al[2][4], bh[4][4], bl[4][4];
#pragma unroll
        for (int mt = 0; mt < 2; mt++) {
            uint32_t r = (uint32_t)(wm * 32 + mt * 16) + lrow;
            ldsm4(ah[mt], sbase + 0 * ARR + r * ROWB + kb);
            ldsm4(al[mt], sbase + 1 * ARR + r * ROWB + kb);
        }
#pragma unroll
        for (int nt = 0; nt < 4; nt++) {
            uint32_t r = (uint32_t)(wn * 64 + nt * 16) + lrow;
            ldsm4(bh[nt], sbase + 2 * ARR + r * ROWB + kb);
            ldsm4(bl[nt], sbase + 3 * ARR + r * ROWB + kb);
        }
#pragma unroll
        for (int mt = 0; mt < 2; mt++)
#pragma unroll
            for (int nt = 0; nt < 4; nt++) {
                float* c0 = acc[mt][nt * 2 + 0];
                float* c1 = acc[mt][nt * 2 + 1];
                mma16816(c0, ah[mt], bh[nt][0], bh[nt][2]);   // hi*hi
                mma16816(c1, ah[mt], bh[nt][1], bh[nt][3]);
                mma16816(c0, al[mt], bh[nt][0], bh[nt][2]);   // lo*hi
                mma16816(c1, al[mt], bh[nt][1], bh[nt][3]);
                mma16816(c0, ah[mt], bl[nt][0], bl[nt][2]);   // hi*lo
                mma16816(c1, ah[mt], bl[nt][1], bl[nt][3]);
            }
    }
}

template <int STRIDE, int NCH>
__device__ __forceinline__ void gemm_main(uint32_t sdyn,
    const __nv_bfloat16* Ah, const __nv_bfloat16* Al,
    const __nv_bfloat16* Bh, const __nv_bfloat16* Bl,
    int wm, int wn, int lane, int tid, float (&acc)[2][8][4])
{
    load_chunk<STRIDE>(sdyn, Ah, Al, Bh, Bl, 0, tid);
    CP_COMMIT();
#pragma unroll
    for (int p = 0; p < NCH; p++) {
        if (p + 1 < NCH) {
            load_chunk<STRIDE>(sdyn + ((p + 1) & 1) * SETSZ, Ah, Al, Bh, Bl, (p + 1) * 64, tid);
            CP_COMMIT();
            CP_WAIT(1);
        } else {
            CP_WAIT(0);
        }
        __syncthreads();
        compute_chunk(sdyn + (p & 1) * SETSZ, wm, wn, lane, acc);
        __syncthreads();
    }
}

// ---------------- kernel 0: zero accumulators ----------------
__global__ void k_zero() {
    int t = threadIdx.x;
    if (t < OUT_DIM) g_colsum[t] = 0.f;
    if (t == 0) { g_sumsq = 0.f; g_loss = 0.0; }
}

// ---------------- kernel 1: split fp32 -> bf16 hi/lo ----------------
__global__ void k_split(const float* __restrict__ src, __nv_bfloat16* __restrict__ h,
                        __nv_bfloat16* __restrict__ l, int n) {
    int i = blockIdx.x * 256 + threadIdx.x;
    if (i < n) {
        float v = src[i];
        __nv_bfloat16 hh = __float2bfloat16(v);
        h[i] = hh;
        l[i] = __float2bfloat16(v - __bfloat162float(hh));
    }
}

// ---------------- kernel 2: outs GEMM (mma.sync bf16 split) ----------------
__global__ __launch_bounds__(256) void k_outs_tc(const float* __restrict__ bias) {
    extern __shared__ char dyn[];
    uint32_t sdyn = smem_u32(dyn);
    const int tid = threadIdx.x, lane = tid & 31, wid = tid >> 5;
    const int wm = wid & 3, wn = wid >> 2;
    const int bn = blockIdx.x, bm = blockIdx.y;

    float acc[2][8][4];
#pragma unroll
    for (int a = 0; a < 2; a++)
#pragma unroll
        for (int b = 0; b < 8; b++)
#pragma unroll
            for (int r = 0; r < 4; r++) acc[a][b][r] = 0.f;

    gemm_main<IN_DIM, 8>(sdyn,
        g_xh + (size_t)bm * 128 * IN_DIM, g_xl + (size_t)bm * 128 * IN_DIM,
        g_Wh + (size_t)bn * 128 * IN_DIM, g_Wl + (size_t)bn * 128 * IN_DIM,
        wm, wn, lane, tid, acc);

#pragma unroll
    for (int mt = 0; mt < 2; mt++) {
        const int rb = bm * 128 + wm * 32 + mt * 16 + (lane >> 2);
#pragma unroll
        for (int n8 = 0; n8 < 8; n8++) {
            const int nb = bn * 128 + wn * 64 + n8 * 8 + (lane & 3) * 2;
            const float2 bs = *(const float2*)&bias[nb];
            const int l = nb >> 8, o = nb & 255;
#pragma unroll
            for (int rp = 0; rp < 2; rp++) {
                const int rr = rb + rp * 8;
                float v0 = acc[mt][n8][rp * 2 + 0] + bs.x;
                float v1 = acc[mt][n8][rp * 2 + 1] + bs.y;
                size_t gi = ((size_t)(l * B_ROWS + rr)) * OUT_DIM + o;
                *(float2*)&g_U[gi] = make_float2(v0, v1);
                __nv_bfloat16 h0 = __float2bfloat16(v0);
                __nv_bfloat16 h1 = __float2bfloat16(v1);
                __nv_bfloat162 hp; hp.x = h0; hp.y = h1;
                *(__nv_bfloat162*)&g_Uh[gi] = hp;
                __nv_bfloat162 lp;
                lp.x = __float2bfloat16(v0 - __bfloat162float(h0));
                lp.y = __float2bfloat16(v1 - __bfloat162float(h1));
                *(__nv_bfloat162*)&g_Ul[gi] = lp;
            }
        }
    }
}

// ---------------- kernel 3: per-row sq norms, colsums, sumsq ----------------
__global__ void k_rowstats() {
    const int tid = threadIdx.x;
    const int r0  = blockIdx.x * 128;
    float cs = 0.f;
    for (int r = 0; r < 128; r++) cs += g_U[(size_t)(r0 + r) * OUT_DIM + tid];
    atomicAdd(&g_colsum[tid], cs);
    int w = tid >> 5, lane = tid & 31;
    float warpsq = 0.f;
    for (int rr = w; rr < 128; rr += 8) {
        const float* row = g_U + (size_t)(r0 + rr) * OUT_DIM;
        float s = 0.f;
#pragma unroll
        for (int c = lane; c < OUT_DIM; c += 32) { float v = row[c]; s = fmaf(v, v, s); }
#pragma unroll
        for (int off = 16; off; off >>= 1) s += __shfl_down_sync(0xffffffffu, s, off);
        if (lane == 0) { g_sq[r0 + rr] = s; warpsq += s; }
    }
    if (lane == 0) atomicAdd(&g_sumsq, warpsq);
}

// ---------------- kernel 4: bandwidth -> exp2 coefficient ----------------
__global__ void k_bw() {
    __shared__ float red[256];
    int t = threadIdx.x;
    float c = g_colsum[t];
    red[t] = c * c;
    __syncthreads();
    for (int s = 128; s; s >>= 1) { if (t < s) red[t] += red[t + s]; __syncthreads(); }
    if (t == 0) {
        double s2 = (double)red[0];
        double sumsq = (double)g_sumsq;
        double n = (double)U_ROWS;
        double bw = (2.0 * n * sumsq - 2.0 * s2) / (n * (n - 1.0));
        g_coef = (float)(-1.4426950408889634 / (4.0 * bw));
    }
}

// ---------------- kernel 5: gates + combine -> d_out ----------------
__global__ void k_gates(const float* __restrict__ x, const float* __restrict__ Waux,
                        const float* __restrict__ baux, float* __restrict__ out) {
    __shared__ float r0s[128], r1s[128];
    const int b = blockIdx.x, t = threadIdx.x;
    float p0 = 0.f, p1 = 0.f;
#pragma unroll
    for (int s = 0; s < 4; s++) {
        float xv = x[(size_t)b * IN_DIM + t + s * 128];
        p0 = fmaf(xv, Waux[t + s * 128], p0);
        p1 = fmaf(xv, Waux[IN_DIM + t + s * 128], p1);
    }
    r0s[t] = p0; r1s[t] = p1;
    __syncthreads();
    for (int s = 64; s; s >>= 1) {
        if (t < s) { r0s[t] += r0s[t + s]; r1s[t] += r1s[t + s]; }
        __syncthreads();
    }
    float l0 = r0s[0] + baux[0];
    float l1 = r1s[0] + baux[1];
    float gg0 = 1.f / (1.f + expf(l1 - l0));
    float gg1 = 1.f - gg0;
#pragma unroll
    for (int s = 0; s < 2; s++) {
        int c = t + s * 128;
        float v = gg0 * g_U[(size_t)b * OUT_DIM + c] +
                  gg1 * g_U[(size_t)(B_ROWS + b) * OUT_DIM + c];
        out[(size_t)b * OUT_DIM + c] = v;
    }
}

// ---------------- kernel 6: pairwise Gram (mma.sync) + kernel-sum ----------------
__global__ __launch_bounds__(256) void k_pair_tc() {
    extern __shared__ char dyn[];
    __shared__ float sSqI[128], sSqJ[128], sRed[8];
    uint32_t sdyn = smem_u32(dyn);
    const int tid = threadIdx.x, lane = tid & 31, wid = tid >> 5;
    const int wm = wid & 3, wn = wid >> 2;

    // upper-triangle decode: blockIdx.x -> (bi, bj), bj >= bi, 64x64 tiles
    int t = blockIdx.x;
    int s = 2079 - t;
    int a = (int)((sqrtf(8.f * (float)s + 1.f) - 1.f) * 0.5f);
    while ((a + 1) * (a + 2) / 2 <= s) a++;
    while (a * (a + 1) / 2 > s) a--;
    const int bi = 63 - a;
    const int bj = 63 - (s - a * (a + 1) / 2);
    const int i0 = bi * 128, j0 = bj * 128;

    if (tid < 128) { sSqI[tid] = g_sq[i0 + tid]; sSqJ[tid] = g_sq[j0 + tid]; }

    float acc[2][8][4];
#pragma unroll
    for (int aa = 0; aa < 2; aa++)
#pragma unroll
        for (int b = 0; b < 8; b++)
#pragma unroll
            for (int r = 0; r < 4; r++) acc[aa][b][r] = 0.f;

    gemm_main<OUT_DIM, 4>(sdyn,
        g_Uh + (size_t)i0 * OUT_DIM, g_Ul + (size_t)i0 * OUT_DIM,
        g_Uh + (size_t)j0 * OUT_DIM, g_Ul + (size_t)j0 * OUT_DIM,
        wm, wn, lane, tid, acc);

    const float coef = g_coef;
    float local = 0.f;
#pragma unroll
    for (int mt = 0; mt < 2; mt++) {
        const int ibase = wm * 32 + mt * 16 + (lane >> 2);
#pragma unroll
        for (int n8 = 0; n8 < 8; n8++) {
            const int jbase = wn * 64 + n8 * 8 + (lane & 3) * 2;
#pragma unroll
            for (int r = 0; r < 4; r++) {
                const int i = ibase + (r >> 1) * 8;
                const int j = jbase + (r & 1);
                const int ig = i0 + i, jg = j0 + j;
                float w = (jg > ig) ? 2.f : (jg == ig ? 1.f : 0.f);
                float d = sSqI[i] + sSqJ[j] - 2.f * acc[mt][n8][r];
                float e = coef * d;
                float u;
                asm("ex2.approx.f32 %0, %1;" : "=f"(u) : "f"(e));
                float u2 = u * u, u4 = u2 * u2, u8 = u4 * u4, u16 = u8 * u8;
                local += w * (u + u2 + u4 + u8 + u16);
            }
        }
    }
#pragma unroll
    for (int off = 16; off; off >>= 1) local += __shfl_down_sync(0xffffffffu, local, off);
    if (lane == 0) sRed[wid] = local;
    __syncthreads();
    if (tid == 0) {
        float tot = 0.f;
#pragma unroll
        for (int ww = 0; ww < 8; ww++) tot += sRed[ww];
        const float sgn = ((bi < 32) == (bj < 32)) ? 1.f : -1.f;
        atomicAdd(&g_loss, (double)tot * (double)sgn);
    }
}

// ---------------- kernel 7: final scalar ----------------
__global__ void k_final(float* __restrict__ out, int idx) {
    if (threadIdx.x == 0)
        out[idx] = (float)(-g_loss / ((double)B_ROWS * (double)B_ROWS));
}

// ---------------- launch ----------------
extern "C" void kernel_launch(void* const* d_in, const int* in_sizes, int n_in,
                              void* d_out, int out_size) {
    const float* x    = (const float*)d_in[0];
    const float* Waux = (const float*)d_in[1];
    const float* baux = (const float*)d_in[2];
    const float* W    = (const float*)d_in[3];  // [2,256,512] == [512,512]
    const float* bias = (const float*)d_in[4];  // [2,256] == [512]
    float* out = (float*)d_out;

    static int attr_done = 0;
    if (!attr_done) {
        cudaFuncSetAttribute(k_outs_tc, cudaFuncAttributeMaxDynamicSharedMemorySize, DYNSZ);
        cudaFuncSetAttribute(k_pair_tc, cudaFuncAttributeMaxDynamicSharedMemorySize, DYNSZ);
        attr_done = 1;
    }

    __nv_bfloat16 *xh, *xl, *Wh, *Wl;
    cudaGetSymbolAddress((void**)&xh, g_xh);
    cudaGetSymbolAddress((void**)&xl, g_xl);
    cudaGetSymbolAddress((void**)&Wh, g_Wh);
    cudaGetSymbolAddress((void**)&Wl, g_Wl);

    k_zero<<<1, 256>>>();
    k_split<<<(B_ROWS * IN_DIM + 255) / 256, 256>>>(x, xh, xl, B_ROWS * IN_DIM);
    k_split<<<(512 * IN_DIM + 255) / 256, 256>>>(W, Wh, Wl, 512 * IN_DIM);
    k_outs_tc<<<dim3(4, 32), 256, DYNSZ>>>(bias);
    k_rowstats<<<64, 256>>>();
    k_bw<<<1, 256>>>();
    k_gates<<<B_ROWS, 128>>>(x, Waux, baux, out);
    k_pair_tc<<<2080, 256, DYNSZ>>>();
    k_final<<<1, 1>>>(out, out_size - 1);
}

// round 4
// speedup vs baseline: 2.1136x; 1.0378x over previous
#include <cuda_runtime.h>
#include <cuda_bf16.h>
#include <cstdint>

#define B_ROWS 4096
#define IN_DIM 512
#define OUT_DIM 256
#define U_ROWS 8192

// ---------------- scratch ----------------
__device__ float          g_U [(size_t)U_ROWS * OUT_DIM];
__device__ __nv_bfloat16  g_Uh[(size_t)U_ROWS * OUT_DIM];
__device__ __nv_bfloat16  g_Ul[(size_t)U_ROWS * OUT_DIM];
__device__ __nv_bfloat16  g_xh[(size_t)B_ROWS * IN_DIM];
__device__ __nv_bfloat16  g_xl[(size_t)B_ROWS * IN_DIM];
__device__ __nv_bfloat16  g_Wh[512 * IN_DIM];
__device__ __nv_bfloat16  g_Wl[512 * IN_DIM];
__device__ float  g_sq[U_ROWS];
__device__ float  g_colsum[OUT_DIM];
__device__ float  g_sumsq;
__device__ double g_loss;
__device__ float  g_coef;

// ---------------- helpers (sm_80-era, family-common PTX only) ----------------
__device__ __forceinline__ uint32_t smem_u32(const void* p) {
    uint32_t a;
    asm("{ .reg .u64 t; cvta.to.shared.u64 t, %1; cvt.u32.u64 %0, t; }" : "=r"(a) : "l"(p));
    return a;
}
__device__ __forceinline__ void ldsm4(uint32_t (&r)[4], uint32_t a) {
    asm volatile("ldmatrix.sync.aligned.m8n8.x4.shared.b16 {%0,%1,%2,%3}, [%4];"
                 : "=r"(r[0]), "=r"(r[1]), "=r"(r[2]), "=r"(r[3]) : "r"(a));
}
__device__ __forceinline__ void mma16816(float* c, const uint32_t* a, uint32_t b0, uint32_t b1) {
    asm volatile("mma.sync.aligned.m16n8k16.row.col.f32.bf16.bf16.f32 "
                 "{%0,%1,%2,%3},{%4,%5,%6,%7},{%8,%9},{%0,%1,%2,%3};"
                 : "+f"(c[0]), "+f"(c[1]), "+f"(c[2]), "+f"(c[3])
                 : "r"(a[0]), "r"(a[1]), "r"(a[2]), "r"(a[3]), "r"(b0), "r"(b1));
}
__device__ __forceinline__ void cp16(uint32_t d, const void* s) {
    asm volatile("cp.async.cg.shared.global [%0], [%1], 16;" :: "r"(d), "l"(s));
}
#define CP_COMMIT() asm volatile("cp.async.commit_group;" ::: "memory")
#define CP_WAIT(n)  asm volatile("cp.async.wait_group %0;" :: "n"(n) : "memory")

// smem: per buffer-set Ah, Al, Bh, Bl; each [128 rows][40 bf16] (80 B pitch, 32 data cols)
#define ROWB   80
#define ARR    10240        // 128 * 80
#define SETSZ  40960        // 4 * ARR
#define DYNSZ  81920        // 2 buffer sets -> 80 KB => 2 CTAs/SM

template <int STRIDE>
__device__ __forceinline__ void load_chunk(uint32_t sbase,
    const __nv_bfloat16* Ah, const __nv_bfloat16* Al,
    const __nv_bfloat16* Bh, const __nv_bfloat16* Bl, int k0, int tid)
{
    const int row0 = tid >> 2;          // 0..63
    const int c    = (tid & 3) * 8;     // 8 bf16 = 16 B
#pragma unroll
    for (int pass = 0; pass < 2; pass++) {
        const int row = row0 + pass * 64;
        const size_t go = (size_t)row * STRIDE + k0 + c;
        const uint32_t so = (uint32_t)(row * ROWB + c * 2);
        cp16(sbase + 0 * ARR + so, Ah + go);
        cp16(sbase + 1 * ARR + so, Al + go);
        cp16(sbase + 2 * ARR + so, Bh + go);
        cp16(sbase + 3 * ARR + so, Bl + go);
    }
}

__device__ __forceinline__ void compute_chunk(uint32_t sbase, int wm, int wn, int lane,
                                              float (&acc)[2][8][4])
{
    const uint32_t lrow  = (uint32_t)(lane & 15);
    const uint32_t khalf = (uint32_t)((lane >> 4) * 16);
#pragma unroll
    for (int ks = 0; ks < 2; ks++) {
        const uint32_t kb = (uint32_t)(ks * 32) + khalf;
        uint32_t ah[2][4], al[2][4];
#pragma unroll
        for (int mt = 0; mt < 2; mt++) {
            uint32_t r = (uint32_t)(wm * 32 + mt * 16) + lrow;
            ldsm4(ah[mt], sbase + 0 * ARR + r * ROWB + kb);
            ldsm4(al[mt], sbase + 1 * ARR + r * ROWB + kb);
        }
#pragma unroll
        for (int nt = 0; nt < 4; nt++) {
            uint32_t bh[4], bl[4];
            uint32_t r = (uint32_t)(wn * 64 + nt * 16) + lrow;
            ldsm4(bh, sbase + 2 * ARR + r * ROWB + kb);
            ldsm4(bl, sbase + 3 * ARR + r * ROWB + kb);
#pragma unroll
            for (int mt = 0; mt < 2; mt++) {
                float* c0 = acc[mt][nt * 2 + 0];
                float* c1 = acc[mt][nt * 2 + 1];
                mma16816(c0, ah[mt], bh[0], bh[2]);   // hi*hi
                mma16816(c1, ah[mt], bh[1], bh[3]);
                mma16816(c0, al[mt], bh[0], bh[2]);   // lo*hi
                mma16816(c1, al[mt], bh[1], bh[3]);
                mma16816(c0, ah[mt], bl[0], bl[2]);   // hi*lo
                mma16816(c1, ah[mt], bl[1], bl[3]);
            }
        }
    }
}

template <int STRIDE, int NCH>
__device__ __forceinline__ void gemm_main(uint32_t sdyn,
    const __nv_bfloat16* Ah, const __nv_bfloat16* Al,
    const __nv_bfloat16* Bh, const __nv_bfloat16* Bl,
    int wm, int wn, int lane, int tid, float (&acc)[2][8][4])
{
    load_chunk<STRIDE>(sdyn, Ah, Al, Bh, Bl, 0, tid);
    CP_COMMIT();
#pragma unroll
    for (int p = 0; p < NCH; p++) {
        if (p + 1 < NCH) {
            load_chunk<STRIDE>(sdyn + ((p + 1) & 1) * SETSZ, Ah, Al, Bh, Bl, (p + 1) * 32, tid);
            CP_COMMIT();
            CP_WAIT(1);
        } else {
            CP_WAIT(0);
        }
        __syncthreads();
        compute_chunk(sdyn + (p & 1) * SETSZ, wm, wn, lane, acc);
        __syncthreads();
    }
}

// ---------------- kernel 0: zero accumulators ----------------
__global__ void k_zero() {
    int t = threadIdx.x;
    if (t < OUT_DIM) g_colsum[t] = 0.f;
    if (t == 0) { g_sumsq = 0.f; g_loss = 0.0; }
}

// ---------------- kernel 1: split fp32 -> bf16 hi/lo ----------------
__global__ void k_split(const float* __restrict__ src, __nv_bfloat16* __restrict__ h,
                        __nv_bfloat16* __restrict__ l, int n) {
    int i = blockIdx.x * 256 + threadIdx.x;
    if (i < n) {
        float v = src[i];
        __nv_bfloat16 hh = __float2bfloat16(v);
        h[i] = hh;
        l[i] = __float2bfloat16(v - __bfloat162float(hh));
    }
}

// ---------------- kernel 2: outs GEMM (mma.sync bf16 split) ----------------
__global__ __launch_bounds__(256, 2) void k_outs_tc(const float* __restrict__ bias) {
    extern __shared__ char dyn[];
    uint32_t sdyn = smem_u32(dyn);
    const int tid = threadIdx.x, lane = tid & 31, wid = tid >> 5;
    const int wm = wid & 3, wn = wid >> 2;
    const int bn = blockIdx.x, bm = blockIdx.y;

    float acc[2][8][4];
#pragma unroll
    for (int a = 0; a < 2; a++)
#pragma unroll
        for (int b = 0; b < 8; b++)
#pragma unroll
            for (int r = 0; r < 4; r++) acc[a][b][r] = 0.f;

    gemm_main<IN_DIM, 16>(sdyn,
        g_xh + (size_t)bm * 128 * IN_DIM, g_xl + (size_t)bm * 128 * IN_DIM,
        g_Wh + (size_t)bn * 128 * IN_DIM, g_Wl + (size_t)bn * 128 * IN_DIM,
        wm, wn, lane, tid, acc);

#pragma unroll
    for (int mt = 0; mt < 2; mt++) {
        const int rb = bm * 128 + wm * 32 + mt * 16 + (lane >> 2);
#pragma unroll
        for (int n8 = 0; n8 < 8; n8++) {
            const int nb = bn * 128 + wn * 64 + n8 * 8 + (lane & 3) * 2;
            const float2 bs = *(const float2*)&bias[nb];
            const int l = nb >> 8, o = nb & 255;
#pragma unroll
            for (int rp = 0; rp < 2; rp++) {
                const int rr = rb + rp * 8;
                float v0 = acc[mt][n8][rp * 2 + 0] + bs.x;
                float v1 = acc[mt][n8][rp * 2 + 1] + bs.y;
                size_t gi = ((size_t)(l * B_ROWS + rr)) * OUT_DIM + o;
                *(float2*)&g_U[gi] = make_float2(v0, v1);
                __nv_bfloat16 h0 = __float2bfloat16(v0);
                __nv_bfloat16 h1 = __float2bfloat16(v1);
                __nv_bfloat162 hp; hp.x = h0; hp.y = h1;
                *(__nv_bfloat162*)&g_Uh[gi] = hp;
                __nv_bfloat162 lp;
                lp.x = __float2bfloat16(v0 - __bfloat162float(h0));
                lp.y = __float2bfloat16(v1 - __bfloat162float(h1));
                *(__nv_bfloat162*)&g_Ul[gi] = lp;
            }
        }
    }
}

// ---------------- kernel 3: per-row sq norms, colsums, sumsq ----------------
__global__ void k_rowstats() {
    const int tid = threadIdx.x;
    const int r0  = blockIdx.x * 128;
    float cs = 0.f;
    for (int r = 0; r < 128; r++) cs += g_U[(size_t)(r0 + r) * OUT_DIM + tid];
    atomicAdd(&g_colsum[tid], cs);
    int w = tid >> 5, lane = tid & 31;
    float warpsq = 0.f;
    for (int rr = w; rr < 128; rr += 8) {
        const float* row = g_U + (size_t)(r0 + rr) * OUT_DIM;
        float s = 0.f;
#pragma unroll
        for (int c = lane; c < OUT_DIM; c += 32) { float v = row[c]; s = fmaf(v, v, s); }
#pragma unroll
        for (int off = 16; off; off >>= 1) s += __shfl_down_sync(0xffffffffu, s, off);
        if (lane == 0) { g_sq[r0 + rr] = s; warpsq += s; }
    }
    if (lane == 0) atomicAdd(&g_sumsq, warpsq);
}

// ---------------- kernel 4: bandwidth -> exp2 coefficient ----------------
__global__ void k_bw() {
    __shared__ float red[256];
    int t = threadIdx.x;
    float c = g_colsum[t];
    red[t] = c * c;
    __syncthreads();
    for (int s = 128; s; s >>= 1) { if (t < s) red[t] += red[t + s]; __syncthreads(); }
    if (t == 0) {
        double s2 = (double)red[0];
        double sumsq = (double)g_sumsq;
        double n = (double)U_ROWS;
        double bw = (2.0 * n * sumsq - 2.0 * s2) / (n * (n - 1.0));
        g_coef = (float)(-1.4426950408889634 / (4.0 * bw));
    }
}

// ---------------- kernel 5: gates + combine -> d_out ----------------
__global__ void k_gates(const float* __restrict__ x, const float* __restrict__ Waux,
                        const float* __restrict__ baux, float* __restrict__ out) {
    __shared__ float r0s[128], r1s[128];
    const int b = blockIdx.x, t = threadIdx.x;
    float p0 = 0.f, p1 = 0.f;
#pragma unroll
    for (int s = 0; s < 4; s++) {
        float xv = x[(size_t)b * IN_DIM + t + s * 128];
        p0 = fmaf(xv, Waux[t + s * 128], p0);
        p1 = fmaf(xv, Waux[IN_DIM + t + s * 128], p1);
    }
    r0s[t] = p0; r1s[t] = p1;
    __syncthreads();
    for (int s = 64; s; s >>= 1) {
        if (t < s) { r0s[t] += r0s[t + s]; r1s[t] += r1s[t + s]; }
        __syncthreads();
    }
    float l0 = r0s[0] + baux[0];
    float l1 = r1s[0] + baux[1];
    float gg0 = 1.f / (1.f + expf(l1 - l0));
    float gg1 = 1.f - gg0;
#pragma unroll
    for (int s = 0; s < 2; s++) {
        int c = t + s * 128;
        float v = gg0 * g_U[(size_t)b * OUT_DIM + c] +
                  gg1 * g_U[(size_t)(B_ROWS + b) * OUT_DIM + c];
        out[(size_t)b * OUT_DIM + c] = v;
    }
}

// ---------------- kernel 6: pairwise Gram (mma.sync) + kernel-sum ----------------
__global__ __launch_bounds__(256, 2) void k_pair_tc() {
    extern __shared__ char dyn[];
    __shared__ float sSqI[128], sSqJ[128], sRed[8];
    uint32_t sdyn = smem_u32(dyn);
    const int tid = threadIdx.x, lane = tid & 31, wid = tid >> 5;
    const int wm = wid & 3, wn = wid >> 2;

    // upper-triangle decode: blockIdx.x -> (bi, bj), bj >= bi, 64x64 tiles
    int t = blockIdx.x;
    int s = 2079 - t;
    int a = (int)((sqrtf(8.f * (float)s + 1.f) - 1.f) * 0.5f);
    while ((a + 1) * (a + 2) / 2 <= s) a++;
    while (a * (a + 1) / 2 > s) a--;
    const int bi = 63 - a;
    const int bj = 63 - (s - a * (a + 1) / 2);
    const int i0 = bi * 128, j0 = bj * 128;

    if (tid < 128) { sSqI[tid] = g_sq[i0 + tid]; sSqJ[tid] = g_sq[j0 + tid]; }

    float acc[2][8][4];
#pragma unroll
    for (int aa = 0; aa < 2; aa++)
#pragma unroll
        for (int b = 0; b < 8; b++)
#pragma unroll
            for (int r = 0; r < 4; r++) acc[aa][b][r] = 0.f;

    gemm_main<OUT_DIM, 8>(sdyn,
        g_Uh + (size_t)i0 * OUT_DIM, g_Ul + (size_t)i0 * OUT_DIM,
        g_Uh + (size_t)j0 * OUT_DIM, g_Ul + (size_t)j0 * OUT_DIM,
        wm, wn, lane, tid, acc);

    const float coef = g_coef;
    float local = 0.f;
#pragma unroll
    for (int mt = 0; mt < 2; mt++) {
        const int ibase = wm * 32 + mt * 16 + (lane >> 2);
#pragma unroll
        for (int n8 = 0; n8 < 8; n8++) {
            const int jbase = wn * 64 + n8 * 8 + (lane & 3) * 2;
#pragma unroll
            for (int r = 0; r < 4; r++) {
                const int i = ibase + (r >> 1) * 8;
                const int j = jbase + (r & 1);
                const int ig = i0 + i, jg = j0 + j;
                float w = (jg > ig) ? 2.f : (jg == ig ? 1.f : 0.f);
                float d = sSqI[i] + sSqJ[j] - 2.f * acc[mt][n8][r];
                float e = coef * d;
                float u;
                asm("ex2.approx.f32 %0, %1;" : "=f"(u) : "f"(e));
                float u2 = u * u, u4 = u2 * u2, u8 = u4 * u4, u16 = u8 * u8;
                local += w * (u + u2 + u4 + u8 + u16);
            }
        }
    }
#pragma unroll
    for (int off = 16; off; off >>= 1) local += __shfl_down_sync(0xffffffffu, local, off);
    if (lane == 0) sRed[wid] = local;
    __syncthreads();
    if (tid == 0) {
        float tot = 0.f;
#pragma unroll
        for (int ww = 0; ww < 8; ww++) tot += sRed[ww];
        const float sgn = ((bi < 32) == (bj < 32)) ? 1.f : -1.f;
        atomicAdd(&g_loss, (double)tot * (double)sgn);
    }
}

// ---------------- kernel 7: final scalar ----------------
__global__ void k_final(float* __restrict__ out, int idx) {
    if (threadIdx.x == 0)
        out[idx] = (float)(-g_loss / ((double)B_ROWS * (double)B_ROWS));
}

// ---------------- launch ----------------
extern "C" void kernel_launch(void* const* d_in, const int* in_sizes, int n_in,
                              void* d_out, int out_size) {
    const float* x    = (const float*)d_in[0];
    const float* Waux = (const float*)d_in[1];
    const float* baux = (const float*)d_in[2];
    const float* W    = (const float*)d_in[3];  // [2,256,512] == [512,512]
    const float* bias = (const float*)d_in[4];  // [2,256] == [512]
    float* out = (float*)d_out;

    cudaFuncSetAttribute(k_outs_tc, cudaFuncAttributeMaxDynamicSharedMemorySize, DYNSZ);
    cudaFuncSetAttribute(k_pair_tc, cudaFuncAttributeMaxDynamicSharedMemorySize, DYNSZ);

    __nv_bfloat16 *xh, *xl, *Wh, *Wl;
    cudaGetSymbolAddress((void**)&xh, g_xh);
    cudaGetSymbolAddress((void**)&xl, g_xl);
    cudaGetSymbolAddress((void**)&Wh, g_Wh);
    cudaGetSymbolAddress((void**)&Wl, g_Wl);

    k_zero<<<1, 256>>>();
    k_split<<<(B_ROWS * IN_DIM + 255) / 256, 256>>>(x, xh, xl, B_ROWS * IN_DIM);
    k_split<<<(512 * IN_DIM + 255) / 256, 256>>>(W, Wh, Wl, 512 * IN_DIM);
    k_outs_tc<<<dim3(4, 32), 256, DYNSZ>>>(bias);
    k_rowstats<<<64, 256>>>();
    k_bw<<<1, 256>>>();
    k_gates<<<B_ROWS, 128>>>(x, Waux, baux, out);
    k_pair_tc<<<2080, 256, DYNSZ>>>();
    k_final<<<1, 1>>>(out, out_size - 1);
}